// round 1
// baseline (speedup 1.0000x reference)
#include <cuda_runtime.h>
#include <cstdint>
#include <cstdio>

// ---------------------------------------------------------------------------
// EdgeModel: out = (relu(relu(X @ W1 + b1) @ W2 + b2)) @ W3 + b3
//   X = concat([src, dest, edge_attr, u[batch]], axis=1)   [E, 512]
//   W1: [512,512], W2: [512,512], W3: [512,128]  (row-major [K][N])
//
// Round-1 implementation: three TF32 mma.sync GEMM launches with __device__
// scratch for h1/h2. Tile 128x128x32, 256 threads, 8 warps (4x2), each warp
// 32x64 via m16n8k8 tf32 fragments.
// ---------------------------------------------------------------------------

#define E_MAX   500000
#define K_DIM   512

// Scratch: 2 x 500000 x 512 fp32 (static device allocations are allowed)
__device__ float g_h1[(size_t)E_MAX * 512];
__device__ float g_h2[(size_t)E_MAX * 512];

__device__ __forceinline__ uint32_t f2tf32(float x) {
    uint32_t r;
    asm("cvt.rna.tf32.f32 %0, %1;" : "=r"(r) : "f"(x));
    return r;
}

__device__ __forceinline__ void mma_tf32(float c[4], const uint32_t a[4],
                                         uint32_t b0, uint32_t b1) {
    asm volatile(
        "mma.sync.aligned.m16n8k8.row.col.f32.tf32.tf32.f32 "
        "{%0,%1,%2,%3}, {%4,%5,%6,%7}, {%8,%9}, {%0,%1,%2,%3};"
        : "+f"(c[0]), "+f"(c[1]), "+f"(c[2]), "+f"(c[3])
        : "r"(a[0]), "r"(a[1]), "r"(a[2]), "r"(a[3]), "r"(b0), "r"(b1));
}

// BM=128, BN=128, BK=32, 256 threads.
// A staged in smem as As[k][m]  (k-major rows, pad 133 for conflict-free STS)
// B staged in smem as Bs[k][n]  (pad 132, multiple of 4 for uint4 STS)
template<bool GATHER, bool RELU>
__global__ __launch_bounds__(256)
void gemm_tf32_kernel(const float* __restrict__ A,
                      const float* __restrict__ src,
                      const float* __restrict__ dst,
                      const float* __restrict__ eat,
                      const float* __restrict__ u,
                      const int*   __restrict__ batch,
                      const float* __restrict__ W,
                      const float* __restrict__ bias,
                      float* __restrict__ C,
                      int M, int N)
{
    __shared__ uint32_t As[32][133];
    __shared__ uint32_t Bs[32][132];

    const int tid  = threadIdx.x;
    const int lane = tid & 31;
    const int warp = tid >> 5;
    const int wm   = warp & 3;   // 4 warps along M -> 32 rows each
    const int wn   = warp >> 2;  // 2 warps along N -> 64 cols each
    const int row0 = blockIdx.y * 128;
    const int n0   = blockIdx.x * 128;

    float acc[2][8][4];
    #pragma unroll
    for (int mt = 0; mt < 2; mt++)
        #pragma unroll
        for (int nt = 0; nt < 8; nt++)
            #pragma unroll
            for (int q = 0; q < 4; q++)
                acc[mt][nt][q] = 0.0f;

    for (int k0 = 0; k0 < K_DIM; k0 += 32) {
        // ---- stage A tile [128 rows x 32 k] (with optional gather/concat) ----
        #pragma unroll
        for (int i = 0; i < 4; i++) {
            int slot = tid + i * 256;          // 1024 float4 slots
            int r    = slot >> 3;              // row within tile (0..127)
            int c4   = (slot & 7) << 2;        // k within chunk (0,4,...,28)
            int grow = row0 + r;
            float4 v = make_float4(0.f, 0.f, 0.f, 0.f);
            if (grow < M) {
                const float* base;
                if (GATHER) {
                    int gk = k0 + c4;          // whole 32-chunk lies in one region
                    if (gk < 128)      base = src + (size_t)grow * 128 + gk;
                    else if (gk < 256) base = dst + (size_t)grow * 128 + (gk - 128);
                    else if (gk < 384) base = eat + (size_t)grow * 128 + (gk - 256);
                    else               base = u + (size_t)batch[grow] * 128 + (gk - 384);
                } else {
                    base = A + (size_t)grow * K_DIM + k0 + c4;
                }
                v = *reinterpret_cast<const float4*>(base);
            }
            As[c4 + 0][r] = f2tf32(v.x);
            As[c4 + 1][r] = f2tf32(v.y);
            As[c4 + 2][r] = f2tf32(v.z);
            As[c4 + 3][r] = f2tf32(v.w);
        }

        // ---- stage B tile [32 k x 128 n] ----
        #pragma unroll
        for (int i = 0; i < 4; i++) {
            int slot = tid + i * 256;
            int kk   = slot >> 5;              // 0..31
            int n4   = (slot & 31) << 2;       // 0,4,...,124
            float4 v = *reinterpret_cast<const float4*>(
                W + (size_t)(k0 + kk) * N + n0 + n4);
            uint4 t;
            t.x = f2tf32(v.x); t.y = f2tf32(v.y);
            t.z = f2tf32(v.z); t.w = f2tf32(v.w);
            *reinterpret_cast<uint4*>(&Bs[kk][n4]) = t;
        }
        __syncthreads();

        // ---- compute: 4 k8-steps of m16n8k8 ----
        #pragma unroll
        for (int ks = 0; ks < 4; ks++) {
            const int kA = ks * 8 + (lane & 3);
            uint32_t a[2][4];
            #pragma unroll
            for (int mt = 0; mt < 2; mt++) {
                int m = wm * 32 + mt * 16 + (lane >> 2);
                a[mt][0] = As[kA][m];
                a[mt][1] = As[kA][m + 8];
                a[mt][2] = As[kA + 4][m];
                a[mt][3] = As[kA + 4][m + 8];
            }
            #pragma unroll
            for (int nt = 0; nt < 8; nt++) {
                int n = wn * 64 + nt * 8 + (lane >> 2);
                uint32_t b0 = Bs[kA][n];
                uint32_t b1 = Bs[kA + 4][n];
                mma_tf32(acc[0][nt], a[0], b0, b1);
                mma_tf32(acc[1][nt], a[1], b0, b1);
            }
        }
        __syncthreads();
    }

    // ---- epilogue: bias (+ReLU) + store ----
    #pragma unroll
    for (int nt = 0; nt < 8; nt++) {
        int col = n0 + wn * 64 + nt * 8 + (lane & 3) * 2;
        float bv0 = bias[col];
        float bv1 = bias[col + 1];
        #pragma unroll
        for (int mt = 0; mt < 2; mt++) {
            int r0 = row0 + wm * 32 + mt * 16 + (lane >> 2);
            float v0 = acc[mt][nt][0] + bv0;
            float v1 = acc[mt][nt][1] + bv1;
            float v2 = acc[mt][nt][2] + bv0;
            float v3 = acc[mt][nt][3] + bv1;
            if (RELU) {
                v0 = fmaxf(v0, 0.f); v1 = fmaxf(v1, 0.f);
                v2 = fmaxf(v2, 0.f); v3 = fmaxf(v3, 0.f);
            }
            if (r0 < M)
                *reinterpret_cast<float2*>(C + (size_t)r0 * N + col) =
                    make_float2(v0, v1);
            if (r0 + 8 < M)
                *reinterpret_cast<float2*>(C + (size_t)(r0 + 8) * N + col) =
                    make_float2(v2, v3);
        }
    }
}

extern "C" void kernel_launch(void* const* d_in, const int* in_sizes, int n_in,
                              void* d_out, int out_size)
{
    const float* src   = (const float*)d_in[0];
    const float* dst   = (const float*)d_in[1];
    const float* eat   = (const float*)d_in[2];
    const float* u     = (const float*)d_in[3];
    const int*   batch = (const int*)  d_in[4];
    const float* W1    = (const float*)d_in[5];
    const float* b1    = (const float*)d_in[6];
    const float* W2    = (const float*)d_in[7];
    const float* b2    = (const float*)d_in[8];
    const float* W3    = (const float*)d_in[9];
    const float* b3    = (const float*)d_in[10];
    float*       out   = (float*)d_out;

    const int M = in_sizes[4];          // E (batch index array length)

    float* h1 = nullptr;
    float* h2 = nullptr;
    cudaGetSymbolAddress((void**)&h1, g_h1);
    cudaGetSymbolAddress((void**)&h2, g_h2);

    dim3 block(256);
    dim3 grid12(4, (M + 127) / 128);    // N = 512
    dim3 grid3 (1, (M + 127) / 128);    // N = 128

    // Layer 1: h1 = relu(X @ W1 + b1), X gathered on the fly
    gemm_tf32_kernel<true, true><<<grid12, block>>>(
        nullptr, src, dst, eat, u, batch, W1, b1, h1, M, 512);

    // Layer 2: h2 = relu(h1 @ W2 + b2)
    gemm_tf32_kernel<false, true><<<grid12, block>>>(
        h1, src, dst, eat, u, batch, W2, b2, h2, M, 512);

    // Layer 3: out = h2 @ W3 + b3
    gemm_tf32_kernel<false, false><<<grid3, block>>>(
        h2, src, dst, eat, u, batch, W3, b3, out, M, 128);
}

// round 3
// speedup vs baseline: 1.8152x; 1.8152x over previous
#include <cuda_runtime.h>
#include <cstdint>

// ============================================================================
// EdgeModel: out = relu(relu(X@W1+b1)@W2+b2)@W3+b3,  X = [src|dest|eat|u[batch]]
// Round 3: tcgen05 TF32 SS-mode GEMMs, with arch-specific feature guards so the
// plain compute_103 gencode pass (which rejects tcgen05) compiles empty stubs.
// The sm_103a cubin (exact match at runtime) carries the real implementation.
// ============================================================================

#if defined(__CUDA_ARCH_FEAT_SM103_ALL) || defined(__CUDA_ARCH_FEAT_SM100_ALL) || \
    defined(__CUDA_ARCH_FEAT_SM101_ALL) || defined(__CUDA_ARCH_SPECIFIC__)   || \
    defined(__CUDA_ARCH_FAMILY_SPECIFIC__)
#define TC_OK 1
#else
#define TC_OK 0
#endif

#define E_MAX 500000

__device__ float    g_h1[(size_t)E_MAX * 512];
__device__ float    g_h2[(size_t)E_MAX * 512];
__device__ uint32_t g_w1i[512 * 512];
__device__ uint32_t g_w2i[512 * 512];
__device__ uint32_t g_w3i[512 * 128];

// ---------------------------------------------------------------------------
#define SWZ(x) ((x) ^ (((x) >> 3) & 0x70))

__device__ __forceinline__ uint32_t f2tf32(float x) {
    uint32_t r; asm("cvt.rna.tf32.f32 %0, %1;" : "=r"(r) : "f"(x)); return r;
}
__device__ __forceinline__ uint32_t smem_u32(const void* p) {
    uint32_t a;
    asm("{ .reg .u64 t; cvta.to.shared.u64 t, %1; cvt.u32.u64 %0, t; }"
        : "=r"(a) : "l"(p));
    return a;
}
__device__ __forceinline__ uint32_t elect1() {
    uint32_t p;
    asm volatile("{ .reg .pred p; elect.sync _|p, 0xFFFFFFFF; selp.b32 %0,1,0,p; }"
                 : "=r"(p));
    return p;
}

// 64-bit SMEM descriptor: SW128, version=1 (Blackwell), LBO=1, SBO=64
static constexpr uint64_t DESC_BASE =
    (2ull << 61) | (1ull << 46) | (64ull << 32) | (1ull << 16);
__device__ __forceinline__ uint64_t mkdesc(uint32_t smem_addr) {
    return DESC_BASE | ((uint64_t)(smem_addr >> 4) & 0x3FFF);
}

// idesc for kind::tf32: dtype=F32(1)<<4, atype=TF32(2)<<7, btype=TF32(2)<<10,
// N/8 <<17, M/16 <<24. Per-dispatch tile is M=128, N=128.
static constexpr uint32_t IDESC_TF32 =
    (1u << 4) | (2u << 7) | (2u << 10) | ((128u / 8) << 17) | ((128u / 16) << 24);

__device__ __forceinline__ void mma_tf32_ss(uint32_t d_tmem, uint64_t a_desc,
                                            uint64_t b_desc, bool acc) {
#if TC_OK
    uint32_t en = acc ? 1u : 0u;
    asm volatile(
        "{\n\t"
        ".reg .pred p;\n\t"
        "setp.ne.u32 p, %4, 0;\n\t"
        "tcgen05.mma.cta_group::1.kind::tf32 [%0], %1, %2, %3, {%5,%5,%5,%5}, p;\n\t"
        "}"
        :: "r"(d_tmem), "l"(a_desc), "l"(b_desc), "r"(IDESC_TF32),
           "r"(en), "r"(0u)
        : "memory");
#endif
}

__device__ __forceinline__ void tc_alloc(uint32_t addr, uint32_t ncols) {
#if TC_OK
    asm volatile("tcgen05.alloc.cta_group::1.sync.aligned.shared::cta.b32 [%0], %1;"
                 :: "r"(addr), "r"(ncols) : "memory");
    asm volatile("tcgen05.relinquish_alloc_permit.cta_group::1.sync.aligned;");
#endif
}
__device__ __forceinline__ void tc_dealloc(uint32_t tmem, uint32_t ncols) {
#if TC_OK
    asm volatile("tcgen05.dealloc.cta_group::1.sync.aligned.b32 %0, %1;"
                 :: "r"(tmem), "r"(ncols));
#endif
}
__device__ __forceinline__ void tc_commit(uint32_t mbar) {
#if TC_OK
    asm volatile("tcgen05.commit.cta_group::1.mbarrier::arrive::one.shared::cluster.b64 [%0];"
                 :: "r"(mbar) : "memory");
#endif
}
__device__ __forceinline__ void tc_wait_ld() {
#if TC_OK
    asm volatile("tcgen05.wait::ld.sync.aligned;" ::: "memory");
#endif
}
__device__ __forceinline__ void tc_fence_after() {
#if TC_OK
    asm volatile("tcgen05.fence::after_thread_sync;" ::: "memory");
#endif
}
__device__ __forceinline__ void fence_async_shared() {
    asm volatile("fence.proxy.async.shared::cta;" ::: "memory");
}
__device__ __forceinline__ void mbar_init(uint32_t addr, uint32_t cnt) {
    asm volatile("mbarrier.init.shared.b64 [%0], %1;" :: "r"(addr), "r"(cnt) : "memory");
}
__device__ __forceinline__ void mbar_wait(uint32_t addr, uint32_t parity) {
    asm volatile(
        "{\n\t"
        ".reg .pred P;\n\t"
        "WL_%=:\n\t"
        "mbarrier.try_wait.parity.acquire.cta.shared::cta.b64 P, [%0], %1, 0x989680;\n\t"
        "@P bra WD_%=;\n\t"
        "bra WL_%=;\n\t"
        "WD_%=:\n\t"
        "}"
        :: "r"(addr), "r"(parity) : "memory");
}
__device__ __forceinline__ void cp16(uint32_t dst, const void* src) {
    asm volatile("cp.async.cg.shared.global [%0], [%1], 16;" :: "r"(dst), "l"(src));
}

__device__ __forceinline__ void ldtm_x32(uint32_t* r, uint32_t addr) {
#if TC_OK
    asm volatile(
        "tcgen05.ld.sync.aligned.32x32b.x32.b32 "
        "{%0,%1,%2,%3,%4,%5,%6,%7,%8,%9,%10,%11,%12,%13,%14,%15,"
        "%16,%17,%18,%19,%20,%21,%22,%23,%24,%25,%26,%27,%28,%29,%30,%31}, [%32];"
        : "=r"(r[0]),  "=r"(r[1]),  "=r"(r[2]),  "=r"(r[3]),
          "=r"(r[4]),  "=r"(r[5]),  "=r"(r[6]),  "=r"(r[7]),
          "=r"(r[8]),  "=r"(r[9]),  "=r"(r[10]), "=r"(r[11]),
          "=r"(r[12]), "=r"(r[13]), "=r"(r[14]), "=r"(r[15]),
          "=r"(r[16]), "=r"(r[17]), "=r"(r[18]), "=r"(r[19]),
          "=r"(r[20]), "=r"(r[21]), "=r"(r[22]), "=r"(r[23]),
          "=r"(r[24]), "=r"(r[25]), "=r"(r[26]), "=r"(r[27]),
          "=r"(r[28]), "=r"(r[29]), "=r"(r[30]), "=r"(r[31])
        : "r"(addr));
#endif
}

// ---------------------------------------------------------------------------
// Prep: W [K=512][N] row-major fp32  ->  pre-swizzled tf32 SMEM-image blocks.
// Block (nt, kc) = 4096 uint32 = [128 n-rows x 32 k] with SW128 swizzle.
// ---------------------------------------------------------------------------
__global__ void prep_weights(const float* __restrict__ W,
                             uint32_t* __restrict__ img, int N) {
    int i = blockIdx.x * blockDim.x + threadIdx.x;
    if (i >= 512 * N) return;
    int k = i / N, n = i % N;
    int nt = n >> 7, kc = k >> 5, nin = n & 127, kin = k & 31;
    img[(size_t)(nt * 16 + kc) * 4096 + (SWZ(nin * 128 + kin * 4) >> 2)] =
        f2tf32(W[i]);
}

// ---------------------------------------------------------------------------
// GEMM: C[tile 128 rows, N = NT*128] = act( A[128, 512] @ Wt + bias )
// MODE 0: A gathered/concatenated from (src, dst, eat, u[batch])
// MODE 1: A = linear fp32 [M][512]
// ---------------------------------------------------------------------------
template<int MODE, int NT, bool RELU>
__global__ __launch_bounds__(256)
void mlp_gemm(const float* __restrict__ A,
              const float* __restrict__ src, const float* __restrict__ dstv,
              const float* __restrict__ eat, const float* __restrict__ u,
              const int* __restrict__ batch,
              const uint32_t* __restrict__ Bimg,
              const float* __restrict__ bias,
              float* __restrict__ C, int M)
{
#if TC_OK
    constexpr int NCOL    = NT * 128;
    constexpr int BSTRIDE = NT * 16384;          // one B chunk (all n-tiles)

    extern __shared__ char dynraw[];
    __shared__ uint32_t s_tptr[1];
    __shared__ alignas(8) uint64_t s_mb[2];

    const int tid  = threadIdx.x;
    const int row0 = blockIdx.x * 128;

    // 1024-align the staging region for SW128 descriptors
    uint32_t dbase = (smem_u32(dynraw) + 1023u) & ~1023u;
    char* dyn = dynraw + (dbase - smem_u32(dynraw));
    const uint32_t abase = dbase;                 // A: 2 x 16KB
    const uint32_t bbase = dbase + 32768;         // B: 2 x BSTRIDE

    if (tid < 32) tc_alloc(smem_u32(s_tptr), 512);
    if (tid == 0) {
        mbar_init(smem_u32(&s_mb[0]), 1);
        mbar_init(smem_u32(&s_mb[1]), 1);
    }
    __syncthreads();
    const uint32_t tmem = s_tptr[0];
    const uint32_t mb0 = smem_u32(&s_mb[0]);
    const uint32_t mb1 = smem_u32(&s_mb[1]);

    int ph0 = 0, ph1 = 0;

    for (int kc = 0; kc < 16; kc++) {
        const int b = kc & 1;
        // wait for MMAs of chunk kc-2 (same buffer) before overwriting
        if (kc >= 2) {
            if (b == 0) { mbar_wait(mb0, ph0 & 1); ph0++; }
            else        { mbar_wait(mb1, ph1 & 1); ph1++; }
        }

        // ---- B: verbatim cp.async of pre-swizzled image blocks ----
        {
            const uint32_t bdst0 = bbase + b * BSTRIDE;
            #pragma unroll
            for (int j = 0; j < NT * 4; j++) {
                int unit = tid + j * 256;          // 16B units
                int nt   = unit >> 10;
                int w_   = unit & 1023;
                cp16(bdst0 + nt * 16384 + w_ * 16,
                     Bimg + (size_t)(nt * 16 + kc) * 4096 + w_ * 4);
            }
        }

        // ---- A: manual gather/convert/swizzle (16 KB) ----
        {
            const uint32_t adst0 = abase + b * 16384;
            #pragma unroll
            for (int i = 0; i < 4; i++) {
                int slot = tid + i * 256;
                int r    = slot >> 3;
                int c4   = (slot & 7) << 2;
                int grow = row0 + r;
                float4 v = make_float4(0.f, 0.f, 0.f, 0.f);
                if (grow < M) {
                    const float* p;
                    if (MODE == 0) {
                        int gk = kc * 32 + c4;
                        if (gk < 128)      p = src  + (size_t)grow * 128 + gk;
                        else if (gk < 256) p = dstv + (size_t)grow * 128 + (gk - 128);
                        else if (gk < 384) p = eat  + (size_t)grow * 128 + (gk - 256);
                        else               p = u + (size_t)batch[grow] * 128 + (gk - 384);
                    } else {
                        p = A + (size_t)grow * 512 + kc * 32 + c4;
                    }
                    v = *reinterpret_cast<const float4*>(p);
                }
                uint4 t;
                t.x = f2tf32(v.x); t.y = f2tf32(v.y);
                t.z = f2tf32(v.z); t.w = f2tf32(v.w);
                *reinterpret_cast<uint4*>(dyn + (adst0 - dbase) + SWZ(r * 128 + c4 * 4)) = t;
            }
        }

        asm volatile("cp.async.commit_group;" ::: "memory");
        asm volatile("cp.async.wait_group 0;" ::: "memory");
        __syncthreads();

        // ---- issue MMAs (warp 0, one elected thread) ----
        if (tid < 32) {
            fence_async_shared();
            if (elect1()) {
                uint64_t ad = mkdesc(abase + b * 16384);
                #pragma unroll
                for (int nt = 0; nt < NT; nt++) {
                    uint64_t bd = mkdesc(bbase + b * BSTRIDE + nt * 16384);
                    #pragma unroll
                    for (int ks = 0; ks < 4; ks++) {
                        mma_tf32_ss(tmem + nt * 128, ad + ks * 2, bd + ks * 2,
                                    !(kc == 0 && ks == 0));
                    }
                }
                tc_commit(b == 0 ? mb0 : mb1);
            }
        }
    }

    // drain both buffers
    mbar_wait(mb0, ph0 & 1);
    mbar_wait(mb1, ph1 & 1);
    tc_fence_after();

    // ---- epilogue: TMEM -> bias(+ReLU) -> gmem fp32 ----
    {
        const int w    = tid >> 5;
        const int lane = tid & 31;
        const int sp   = w & 3;                  // SMSP / TMEM subpartition
        const int row  = row0 + sp * 32 + lane;
        const int cb0  = (w >> 2) * (NCOL / 2);  // col split between warp groups

        #pragma unroll
        for (int g = 0; g < NCOL / 64; g++) {
            const int col = cb0 + g * 32;
            uint32_t regs[32];
            ldtm_x32(regs, tmem + col);
            tc_wait_ld();
            if (row < M) {
                #pragma unroll
                for (int q = 0; q < 8; q++) {
                    float4 bv = *reinterpret_cast<const float4*>(bias + col + q * 4);
                    float4 o;
                    o.x = __uint_as_float(regs[q * 4 + 0]) + bv.x;
                    o.y = __uint_as_float(regs[q * 4 + 1]) + bv.y;
                    o.z = __uint_as_float(regs[q * 4 + 2]) + bv.z;
                    o.w = __uint_as_float(regs[q * 4 + 3]) + bv.w;
                    if (RELU) {
                        o.x = fmaxf(o.x, 0.f); o.y = fmaxf(o.y, 0.f);
                        o.z = fmaxf(o.z, 0.f); o.w = fmaxf(o.w, 0.f);
                    }
                    *reinterpret_cast<float4*>(C + (size_t)row * NCOL + col + q * 4) = o;
                }
            }
        }
    }

    __syncthreads();
    if (tid < 32) tc_dealloc(tmem, 512);
#endif  // TC_OK
}

// ---------------------------------------------------------------------------
extern "C" void kernel_launch(void* const* d_in, const int* in_sizes, int n_in,
                              void* d_out, int out_size)
{
    const float* src   = (const float*)d_in[0];
    const float* dstv  = (const float*)d_in[1];
    const float* eat   = (const float*)d_in[2];
    const float* u     = (const float*)d_in[3];
    const int*   batch = (const int*)  d_in[4];
    const float* W1    = (const float*)d_in[5];
    const float* b1    = (const float*)d_in[6];
    const float* W2    = (const float*)d_in[7];
    const float* b2    = (const float*)d_in[8];
    const float* W3    = (const float*)d_in[9];
    const float* b3    = (const float*)d_in[10];
    float*       out   = (float*)d_out;

    const int M = in_sizes[4];

    float *h1, *h2;
    uint32_t *w1i, *w2i, *w3i;
    cudaGetSymbolAddress((void**)&h1,  g_h1);
    cudaGetSymbolAddress((void**)&h2,  g_h2);
    cudaGetSymbolAddress((void**)&w1i, g_w1i);
    cudaGetSymbolAddress((void**)&w2i, g_w2i);
    cudaGetSymbolAddress((void**)&w3i, g_w3i);

    static bool attr_done = false;
    if (!attr_done) {
        cudaFuncSetAttribute(mlp_gemm<0, 4, true>,
            cudaFuncAttributeMaxDynamicSharedMemorySize, 164864);
        cudaFuncSetAttribute(mlp_gemm<1, 4, true>,
            cudaFuncAttributeMaxDynamicSharedMemorySize, 164864);
        cudaFuncSetAttribute(mlp_gemm<1, 1, false>,
            cudaFuncAttributeMaxDynamicSharedMemorySize, 66560);
        attr_done = true;
    }

    // weight prep (tiny)
    prep_weights<<<(512 * 512 + 255) / 256, 256>>>(W1, w1i, 512);
    prep_weights<<<(512 * 512 + 255) / 256, 256>>>(W2, w2i, 512);
    prep_weights<<<(512 * 128 + 255) / 256, 256>>>(W3, w3i, 128);

    const int tiles = (M + 127) / 128;

    // layer 1: h1 = relu(X @ W1 + b1)   (gathered A)
    mlp_gemm<0, 4, true><<<tiles, 256, 164864>>>(
        nullptr, src, dstv, eat, u, batch, w1i, b1, h1, M);

    // layer 2: h2 = relu(h1 @ W2 + b2)
    mlp_gemm<1, 4, true><<<tiles, 256, 164864>>>(
        h1, nullptr, nullptr, nullptr, nullptr, nullptr, w2i, b2, h2, M);

    // layer 3: out = h2 @ W3 + b3
    mlp_gemm<1, 1, false><<<tiles, 256, 66560>>>(
        h2, nullptr, nullptr, nullptr, nullptr, nullptr, w3i, b3, out, M);
}

// round 4
// speedup vs baseline: 2.2007x; 1.2124x over previous
#include <cuda_runtime.h>
#include <cstdint>

// ============================================================================
// EdgeModel round 4: tcgen05 TF32, warp-specialized mbarrier pipelines,
// fused layers 2+3, h1 kept as pre-swizzled tf32 image.
// ============================================================================

#if defined(__CUDA_ARCH_FEAT_SM103_ALL) || defined(__CUDA_ARCH_FEAT_SM100_ALL) || \
    defined(__CUDA_ARCH_FEAT_SM101_ALL) || defined(__CUDA_ARCH_SPECIFIC__)   || \
    defined(__CUDA_ARCH_FAMILY_SPECIFIC__)
#define TC_OK 1
#else
#define TC_OK 0
#endif

#define E_MAX  500000
#define TMAX   3907          // ceil(500000/128)

// h1 image: per tile, 16 chunks of 4096 u32 (16KB swizzled [128r x 32k] tf32)
__device__ uint32_t g_h1i[(size_t)TMAX * 16 * 4096];
__device__ uint32_t g_w1i[512 * 512];
__device__ uint32_t g_w2i[512 * 512];
__device__ uint32_t g_w3i[512 * 128];

// ---------------------------------------------------------------------------
#define SWZ(x) ((x) ^ (((x) >> 3) & 0x70))

__device__ __forceinline__ uint32_t f2tf32(float x) {
    uint32_t r; asm("cvt.rna.tf32.f32 %0, %1;" : "=r"(r) : "f"(x)); return r;
}
__device__ __forceinline__ uint32_t smem_u32(const void* p) {
    uint32_t a;
    asm("{ .reg .u64 t; cvta.to.shared.u64 t, %1; cvt.u32.u64 %0, t; }"
        : "=r"(a) : "l"(p));
    return a;
}
__device__ __forceinline__ uint32_t elect1() {
    uint32_t p;
    asm volatile("{ .reg .pred p; elect.sync _|p, 0xFFFFFFFF; selp.b32 %0,1,0,p; }"
                 : "=r"(p));
    return p;
}

static constexpr uint64_t DESC_BASE =
    (2ull << 61) | (1ull << 46) | (64ull << 32) | (1ull << 16);
__device__ __forceinline__ uint64_t mkdesc(uint32_t smem_addr) {
    return DESC_BASE | ((uint64_t)(smem_addr >> 4) & 0x3FFF);
}

// idesc kind::tf32: dtype=F32, a/b=TF32, N=128, M=128
static constexpr uint32_t IDESC_TF32 =
    (1u << 4) | (2u << 7) | (2u << 10) | ((128u / 8) << 17) | ((128u / 16) << 24);

__device__ __forceinline__ void mma_tf32_ss(uint32_t d_tmem, uint64_t a_desc,
                                            uint64_t b_desc, bool acc) {
#if TC_OK
    uint32_t en = acc ? 1u : 0u;
    asm volatile(
        "{\n\t"
        ".reg .pred p;\n\t"
        "setp.ne.u32 p, %4, 0;\n\t"
        "tcgen05.mma.cta_group::1.kind::tf32 [%0], %1, %2, %3, {%5,%5,%5,%5}, p;\n\t"
        "}"
        :: "r"(d_tmem), "l"(a_desc), "l"(b_desc), "r"(IDESC_TF32),
           "r"(en), "r"(0u)
        : "memory");
#endif
}

__device__ __forceinline__ void tc_alloc(uint32_t addr, uint32_t ncols) {
#if TC_OK
    asm volatile("tcgen05.alloc.cta_group::1.sync.aligned.shared::cta.b32 [%0], %1;"
                 :: "r"(addr), "r"(ncols) : "memory");
    asm volatile("tcgen05.relinquish_alloc_permit.cta_group::1.sync.aligned;");
#endif
}
__device__ __forceinline__ void tc_dealloc(uint32_t tmem, uint32_t ncols) {
#if TC_OK
    asm volatile("tcgen05.dealloc.cta_group::1.sync.aligned.b32 %0, %1;"
                 :: "r"(tmem), "r"(ncols));
#endif
}
__device__ __forceinline__ void tc_commit(uint32_t mbar) {
#if TC_OK
    asm volatile("tcgen05.commit.cta_group::1.mbarrier::arrive::one.shared::cluster.b64 [%0];"
                 :: "r"(mbar) : "memory");
#endif
}
__device__ __forceinline__ void tc_wait_ld() {
#if TC_OK
    asm volatile("tcgen05.wait::ld.sync.aligned;" ::: "memory");
#endif
}
__device__ __forceinline__ void tc_fence_after() {
#if TC_OK
    asm volatile("tcgen05.fence::after_thread_sync;" ::: "memory");
#endif
}
__device__ __forceinline__ void fence_async_shared() {
    asm volatile("fence.proxy.async.shared::cta;" ::: "memory");
}
__device__ __forceinline__ void mbar_init(uint32_t addr, uint32_t cnt) {
    asm volatile("mbarrier.init.shared.b64 [%0], %1;" :: "r"(addr), "r"(cnt) : "memory");
}
__device__ __forceinline__ void mbar_arrive(uint32_t addr) {
    asm volatile("mbarrier.arrive.shared.b64 _, [%0];" :: "r"(addr) : "memory");
}
__device__ __forceinline__ void mbar_expect_tx(uint32_t addr, uint32_t bytes) {
    asm volatile("mbarrier.arrive.expect_tx.shared.b64 _, [%0], %1;"
                 :: "r"(addr), "r"(bytes) : "memory");
}
__device__ __forceinline__ void mbar_wait(uint32_t addr, uint32_t parity) {
    asm volatile(
        "{\n\t"
        ".reg .pred P;\n\t"
        "WL_%=:\n\t"
        "mbarrier.try_wait.parity.acquire.cta.shared::cta.b64 P, [%0], %1, 0x989680;\n\t"
        "@P bra WD_%=;\n\t"
        "bra WL_%=;\n\t"
        "WD_%=:\n\t"
        "}"
        :: "r"(addr), "r"(parity) : "memory");
}
__device__ __forceinline__ void bulk_g2s(uint32_t dst, const void* src,
                                         uint32_t bytes, uint32_t mbar) {
    asm volatile("cp.async.bulk.shared::cta.global.mbarrier::complete_tx::bytes "
                 "[%0], [%1], %2, [%3];"
                 :: "r"(dst), "l"(src), "r"(bytes), "r"(mbar) : "memory");
}

__device__ __forceinline__ void ldtm_x32(uint32_t* r, uint32_t addr) {
#if TC_OK
    asm volatile(
        "tcgen05.ld.sync.aligned.32x32b.x32.b32 "
        "{%0,%1,%2,%3,%4,%5,%6,%7,%8,%9,%10,%11,%12,%13,%14,%15,"
        "%16,%17,%18,%19,%20,%21,%22,%23,%24,%25,%26,%27,%28,%29,%30,%31}, [%32];"
        : "=r"(r[0]),  "=r"(r[1]),  "=r"(r[2]),  "=r"(r[3]),
          "=r"(r[4]),  "=r"(r[5]),  "=r"(r[6]),  "=r"(r[7]),
          "=r"(r[8]),  "=r"(r[9]),  "=r"(r[10]), "=r"(r[11]),
          "=r"(r[12]), "=r"(r[13]), "=r"(r[14]), "=r"(r[15]),
          "=r"(r[16]), "=r"(r[17]), "=r"(r[18]), "=r"(r[19]),
          "=r"(r[20]), "=r"(r[21]), "=r"(r[22]), "=r"(r[23]),
          "=r"(r[24]), "=r"(r[25]), "=r"(r[26]), "=r"(r[27]),
          "=r"(r[28]), "=r"(r[29]), "=r"(r[30]), "=r"(r[31])
        : "r"(addr));
#endif
}

// ---------------------------------------------------------------------------
// prep: W [512][N] row-major fp32 -> tf32 pre-swizzled SMEM-image blocks
// ---------------------------------------------------------------------------
__global__ void prep_weights(const float* __restrict__ W,
                             uint32_t* __restrict__ img, int N) {
    int i = blockIdx.x * blockDim.x + threadIdx.x;
    if (i >= 512 * N) return;
    int k = i / N, n = i % N;
    int nt = n >> 7, kc = k >> 5, nin = n & 127, kin = k & 31;
    img[(size_t)(nt * 16 + kc) * 4096 + (SWZ(nin * 128 + kin * 4) >> 2)] =
        f2tf32(W[i]);
}

// ---------------------------------------------------------------------------
// GEMM1: h1img[tile] = swizzled_tf32( relu( gather(X) @ W1 + b1 ) )
// warp 0: MMA issue | warp 1: B bulk producer | warps 4-7: A gather producers
// ---------------------------------------------------------------------------
__global__ __launch_bounds__(256)
void gemm1_kernel(const float* __restrict__ src, const float* __restrict__ dstv,
                  const float* __restrict__ eat, const float* __restrict__ u,
                  const int* __restrict__ batch,
                  const uint32_t* __restrict__ w1img,
                  const float* __restrict__ b1,
                  uint32_t* __restrict__ h1img, int M)
{
#if TC_OK
    extern __shared__ char dynraw[];
    __shared__ uint32_t s_tptr[1];
    __shared__ alignas(8) uint64_t s_bars[7];   // fA0 fA1 fB0 fB1 eAB0 eAB1 mbF

    const int tid  = threadIdx.x;
    const int warp = tid >> 5;
    const int lane = tid & 31;
    const int tile = blockIdx.x;
    const int row0 = tile * 128;

    uint32_t dbase = (smem_u32(dynraw) + 1023u) & ~1023u;
    char* dyn = dynraw + (dbase - smem_u32(dynraw));
    const uint32_t abase = dbase;                 // 2 x 16KB
    const uint32_t bbase = dbase + 32768;         // 2 x 64KB

    if (warp == 0) tc_alloc(smem_u32(s_tptr), 512);
    if (tid == 0) {
        mbar_init(smem_u32(&s_bars[0]), 128);   // fA0
        mbar_init(smem_u32(&s_bars[1]), 128);   // fA1
        mbar_init(smem_u32(&s_bars[2]), 1);     // fB0
        mbar_init(smem_u32(&s_bars[3]), 1);     // fB1
        mbar_init(smem_u32(&s_bars[4]), 1);     // eAB0
        mbar_init(smem_u32(&s_bars[5]), 1);     // eAB1
        mbar_init(smem_u32(&s_bars[6]), 1);     // mbF
    }
    __syncthreads();
    const uint32_t tmem = s_tptr[0];
    const uint32_t fA[2]  = { smem_u32(&s_bars[0]), smem_u32(&s_bars[1]) };
    const uint32_t fB[2]  = { smem_u32(&s_bars[2]), smem_u32(&s_bars[3]) };
    const uint32_t eAB[2] = { smem_u32(&s_bars[4]), smem_u32(&s_bars[5]) };
    const uint32_t mbF    = smem_u32(&s_bars[6]);

    if (warp == 1) {
        // ---- B producer: verbatim bulk copies of pre-swizzled w1 image ----
        if (elect1()) {
            int ph[2] = {0, 0};
            for (int kc = 0; kc < 16; kc++) {
                const int b = kc & 1;
                if (kc >= 2) { mbar_wait(eAB[b], ph[b] & 1); ph[b]++; }
                mbar_expect_tx(fB[b], 65536);
                #pragma unroll
                for (int nt = 0; nt < 4; nt++)
                    bulk_g2s(bbase + b * 65536 + nt * 16384,
                             w1img + (size_t)(nt * 16 + kc) * 4096, 16384, fB[b]);
            }
        }
    } else if (warp >= 4) {
        // ---- A producers: gather + cvt + swizzled STS ----
        const int tp = tid - 128;
        int ph[2] = {0, 0};
        for (int kc = 0; kc < 16; kc++) {
            const int b = kc & 1;
            if (kc >= 2) { mbar_wait(eAB[b], ph[b] & 1); ph[b]++; }
            #pragma unroll
            for (int i = 0; i < 8; i++) {
                int slot = tp + i * 128;
                int r    = slot >> 3;
                int c4   = (slot & 7) << 2;
                int grow = row0 + r;
                float4 v = make_float4(0.f, 0.f, 0.f, 0.f);
                if (grow < M) {
                    const float* p;
                    int gk = kc * 32 + c4;
                    if (gk < 128)      p = src  + (size_t)grow * 128 + gk;
                    else if (gk < 256) p = dstv + (size_t)grow * 128 + (gk - 128);
                    else if (gk < 384) p = eat  + (size_t)grow * 128 + (gk - 256);
                    else               p = u + (size_t)batch[grow] * 128 + (gk - 384);
                    v = *reinterpret_cast<const float4*>(p);
                }
                uint4 t;
                t.x = f2tf32(v.x); t.y = f2tf32(v.y);
                t.z = f2tf32(v.z); t.w = f2tf32(v.w);
                *reinterpret_cast<uint4*>(dyn + b * 16384 + SWZ(r * 128 + c4 * 4)) = t;
            }
            fence_async_shared();
            mbar_arrive(fA[b]);
        }
    } else if (warp == 0) {
        // ---- MMA issuer ----
        if (elect1()) {
            int phA[2] = {0, 0}, phB[2] = {0, 0};
            for (int kc = 0; kc < 16; kc++) {
                const int b = kc & 1;
                mbar_wait(fA[b], phA[b] & 1); phA[b]++;
                mbar_wait(fB[b], phB[b] & 1); phB[b]++;
                uint64_t ad = mkdesc(abase + b * 16384);
                #pragma unroll
                for (int nt = 0; nt < 4; nt++) {
                    uint64_t bd = mkdesc(bbase + b * 65536 + nt * 16384);
                    #pragma unroll
                    for (int ks = 0; ks < 4; ks++)
                        mma_tf32_ss(tmem + nt * 128, ad + ks * 2, bd + ks * 2,
                                    !(kc == 0 && ks == 0));
                }
                tc_commit(kc == 15 ? mbF : eAB[b]);
            }
        }
    }

    // ---- epilogue: D1 + b1, relu, cvt, write swizzled h1 image ----
    mbar_wait(mbF, 0);
    tc_fence_after();
    {
        const int sp  = warp & 3;
        const int r   = sp * 32 + lane;          // row within tile
        const int cb0 = (warp >> 2) * 256;
        #pragma unroll
        for (int g = 0; g < 8; g++) {
            const int col = cb0 + g * 32;
            uint32_t regs[32];
            ldtm_x32(regs, tmem + col);
            tc_wait_ld();
            uint32_t* blk = h1img + ((size_t)tile * 16 + (col >> 5)) * 4096;
            #pragma unroll
            for (int q = 0; q < 8; q++) {
                float4 bv = *reinterpret_cast<const float4*>(b1 + col + q * 4);
                uint4 t;
                t.x = f2tf32(fmaxf(__uint_as_float(regs[q*4+0]) + bv.x, 0.f));
                t.y = f2tf32(fmaxf(__uint_as_float(regs[q*4+1]) + bv.y, 0.f));
                t.z = f2tf32(fmaxf(__uint_as_float(regs[q*4+2]) + bv.z, 0.f));
                t.w = f2tf32(fmaxf(__uint_as_float(regs[q*4+3]) + bv.w, 0.f));
                *reinterpret_cast<uint4*>(blk + (SWZ(r * 128 + q * 16) >> 2)) = t;
            }
        }
    }
    __syncthreads();
    if (warp == 0) tc_dealloc(tmem, 512);
#endif
}

// ---------------------------------------------------------------------------
// GEMM2+3 fused: D2 = h1 @ W2 (TMEM 512 cols); evacuate D2 in 4 groups
// through bias+relu into SMEM tf32 images; GEMM3 accumulates D3 into
// TMEM cols [0,128); final epilogue: out = D3 + b3.
// warp 0: MMA + evac | warps 1-3: evac | warp 4: bulk producer
// ---------------------------------------------------------------------------
__global__ __launch_bounds__(256)
void gemm23_kernel(const uint32_t* __restrict__ h1img,
                   const uint32_t* __restrict__ w2img,
                   const float* __restrict__ b2,
                   const uint32_t* __restrict__ w3img,
                   const float* __restrict__ b3,
                   float* __restrict__ out, int M)
{
#if TC_OK
    extern __shared__ char dynraw[];
    __shared__ uint32_t s_tptr[1];
    __shared__ alignas(8) uint64_t s_bars[11];
    // 0:fA0 1:fA1 2:fB0 3:fB1 4:eAB0 5:eAB1 6:mbF2 7:fB3_0 8:fB3_1 9:eG3 10:mbF3

    const int tid  = threadIdx.x;
    const int warp = tid >> 5;
    const int lane = tid & 31;
    const int tile = blockIdx.x;
    const int row0 = tile * 128;

    uint32_t dbase = (smem_u32(dynraw) + 1023u) & ~1023u;
    char* dyn = dynraw + (dbase - smem_u32(dynraw));
    // region0 [0,64KB): GEMM2 A ring (2x16KB) then reused as A3 (4x16KB)
    // region1 [64KB,192KB): B ring (2x64KB), reused for B3 groups
    const uint32_t abase = dbase;
    const uint32_t bbase = dbase + 65536;
    (void)dyn;

    if (warp == 0) tc_alloc(smem_u32(s_tptr), 512);
    if (tid == 0) {
        for (int i = 0; i < 11; i++)
            mbar_init(smem_u32(&s_bars[i]), 1);
    }
    __syncthreads();
    const uint32_t tmem = s_tptr[0];
    const uint32_t fA[2]  = { smem_u32(&s_bars[0]), smem_u32(&s_bars[1]) };
    const uint32_t fB[2]  = { smem_u32(&s_bars[2]), smem_u32(&s_bars[3]) };
    const uint32_t eAB[2] = { smem_u32(&s_bars[4]), smem_u32(&s_bars[5]) };
    const uint32_t mbF2   = smem_u32(&s_bars[6]);
    const uint32_t fB3[2] = { smem_u32(&s_bars[7]), smem_u32(&s_bars[8]) };
    const uint32_t eG3    = smem_u32(&s_bars[9]);
    const uint32_t mbF3   = smem_u32(&s_bars[10]);

    if (warp == 4) {
        if (elect1()) {
            // ---- GEMM2 producer: A2 (h1 image) + B2 (w2 image) ----
            int ph[2] = {0, 0};
            for (int kc = 0; kc < 16; kc++) {
                const int b = kc & 1;
                if (kc >= 2) { mbar_wait(eAB[b], ph[b] & 1); ph[b]++; }
                mbar_expect_tx(fA[b], 16384);
                bulk_g2s(abase + b * 16384,
                         h1img + ((size_t)tile * 16 + kc) * 4096, 16384, fA[b]);
                mbar_expect_tx(fB[b], 65536);
                #pragma unroll
                for (int nt = 0; nt < 4; nt++)
                    bulk_g2s(bbase + b * 65536 + nt * 16384,
                             w2img + (size_t)(nt * 16 + kc) * 4096, 16384, fB[b]);
            }
            // ---- B3 producer: 4 groups of 64KB (contiguous in w3 image) ----
            mbar_wait(mbF2, 0);
            int phg = 0;
            for (int g = 0; g < 4; g++) {
                const int s = g & 1;
                if (g >= 2) { mbar_wait(eG3, phg & 1); phg++; }
                mbar_expect_tx(fB3[s], 65536);
                bulk_g2s(bbase + s * 65536, w3img + (size_t)g * 16384, 65536, fB3[s]);
            }
        }
    }

    if (warp == 0) {
        // ---- GEMM2 MMA issuer ----
        if (elect1()) {
            int phA[2] = {0, 0}, phB[2] = {0, 0};
            for (int kc = 0; kc < 16; kc++) {
                const int b = kc & 1;
                mbar_wait(fA[b], phA[b] & 1); phA[b]++;
                mbar_wait(fB[b], phB[b] & 1); phB[b]++;
                uint64_t ad = mkdesc(abase + b * 16384);
                #pragma unroll
                for (int nt = 0; nt < 4; nt++) {
                    uint64_t bd = mkdesc(bbase + b * 65536 + nt * 16384);
                    #pragma unroll
                    for (int ks = 0; ks < 4; ks++)
                        mma_tf32_ss(tmem + nt * 128, ad + ks * 2, bd + ks * 2,
                                    !(kc == 0 && ks == 0));
                }
                tc_commit(kc == 15 ? mbF2 : eAB[b]);
            }
        }
    }

    // ---- GEMM3: evac D2 group g -> A3 images; MMA k-group g into D3 ----
    if (warp < 4) {
        mbar_wait(mbF2, 0);
        tc_fence_after();
        const int r = warp * 32 + lane;
        int phb3[2] = {0, 0};
        for (int g = 0; g < 4; g++) {
            if (g >= 1) mbar_wait(eG3, (g - 1) & 1);   // A3 free (MMA g-1 done)
            #pragma unroll
            for (int j = 0; j < 4; j++) {
                uint32_t regs[32];
                ldtm_x32(regs, tmem + g * 128 + j * 32);
                tc_wait_ld();
                const int colb = g * 128 + j * 32;
                #pragma unroll
                for (int q = 0; q < 8; q++) {
                    float4 bv = *reinterpret_cast<const float4*>(b2 + colb + q * 4);
                    uint4 t;
                    t.x = f2tf32(fmaxf(__uint_as_float(regs[q*4+0]) + bv.x, 0.f));
                    t.y = f2tf32(fmaxf(__uint_as_float(regs[q*4+1]) + bv.y, 0.f));
                    t.z = f2tf32(fmaxf(__uint_as_float(regs[q*4+2]) + bv.z, 0.f));
                    t.w = f2tf32(fmaxf(__uint_as_float(regs[q*4+3]) + bv.w, 0.f));
                    *reinterpret_cast<uint4*>(
                        dyn + j * 16384 + SWZ(r * 128 + q * 16)) = t;
                }
            }
            fence_async_shared();
            asm volatile("bar.sync 1, 128;" ::: "memory");
            if (warp == 0 && elect1()) {
                const int s = g & 1;
                mbar_wait(fB3[s], phb3[s] & 1); phb3[s]++;
                #pragma unroll
                for (int j = 0; j < 4; j++) {
                    uint64_t ad = mkdesc(abase + j * 16384);
                    uint64_t bd = mkdesc(bbase + s * 65536 + j * 16384);
                    #pragma unroll
                    for (int ks = 0; ks < 4; ks++)
                        mma_tf32_ss(tmem, ad + ks * 2, bd + ks * 2,
                                    !(g == 0 && j == 0 && ks == 0));
                }
                tc_commit(g == 3 ? mbF3 : eG3);
            }
        }
    }

    // ---- final epilogue: out = D3 + b3 ----
    mbar_wait(mbF3, 0);
    tc_fence_after();
    {
        const int sp  = warp & 3;
        const int row = row0 + sp * 32 + lane;
        const int cb0 = (warp >> 2) * 64;
        #pragma unroll
        for (int gg = 0; gg < 2; gg++) {
            const int col = cb0 + gg * 32;
            uint32_t regs[32];
            ldtm_x32(regs, tmem + col);
            tc_wait_ld();
            if (row < M) {
                #pragma unroll
                for (int q = 0; q < 8; q++) {
                    float4 bv = *reinterpret_cast<const float4*>(b3 + col + q * 4);
                    float4 o;
                    o.x = __uint_as_float(regs[q*4+0]) + bv.x;
                    o.y = __uint_as_float(regs[q*4+1]) + bv.y;
                    o.z = __uint_as_float(regs[q*4+2]) + bv.z;
                    o.w = __uint_as_float(regs[q*4+3]) + bv.w;
                    *reinterpret_cast<float4*>(out + (size_t)row * 128 + col + q * 4) = o;
                }
            }
        }
    }
    __syncthreads();
    if (warp == 0) tc_dealloc(tmem, 512);
#endif
}

// ---------------------------------------------------------------------------
extern "C" void kernel_launch(void* const* d_in, const int* in_sizes, int n_in,
                              void* d_out, int out_size)
{
    const float* src   = (const float*)d_in[0];
    const float* dstv  = (const float*)d_in[1];
    const float* eat   = (const float*)d_in[2];
    const float* u     = (const float*)d_in[3];
    const int*   batch = (const int*)  d_in[4];
    const float* W1    = (const float*)d_in[5];
    const float* b1    = (const float*)d_in[6];
    const float* W2    = (const float*)d_in[7];
    const float* b2    = (const float*)d_in[8];
    const float* W3    = (const float*)d_in[9];
    const float* b3    = (const float*)d_in[10];
    float*       out   = (float*)d_out;

    const int M = in_sizes[4];

    uint32_t *h1i, *w1i, *w2i, *w3i;
    cudaGetSymbolAddress((void**)&h1i, g_h1i);
    cudaGetSymbolAddress((void**)&w1i, g_w1i);
    cudaGetSymbolAddress((void**)&w2i, g_w2i);
    cudaGetSymbolAddress((void**)&w3i, g_w3i);

    static bool attr_done = false;
    if (!attr_done) {
        cudaFuncSetAttribute(gemm1_kernel,
            cudaFuncAttributeMaxDynamicSharedMemorySize, 164864);
        cudaFuncSetAttribute(gemm23_kernel,
            cudaFuncAttributeMaxDynamicSharedMemorySize, 197632);
        attr_done = true;
    }

    prep_weights<<<(512 * 512 + 255) / 256, 256>>>(W1, w1i, 512);
    prep_weights<<<(512 * 512 + 255) / 256, 256>>>(W2, w2i, 512);
    prep_weights<<<(512 * 128 + 255) / 256, 256>>>(W3, w3i, 128);

    const int tiles = (M + 127) / 128;

    gemm1_kernel<<<tiles, 256, 164864>>>(
        src, dstv, eat, u, batch, w1i, b1, h1i, M);

    gemm23_kernel<<<tiles, 256, 197632>>>(
        h1i, w2i, b2, w3i, b3, out, M);
}